// round 16
// baseline (speedup 1.0000x reference)
#include <cuda_runtime.h>
#include <cuda_fp16.h>
#include <math.h>
#include <stdint.h>

#define N_NODES 16000
#define N_EDGES 64000
#define HH 90
#define F0 16
#define EF 8
#define NGR 512
#define H2 45
#define CAP 64
#define NCP_MAX 9216
#define KP_MAX 96
#define NCB 4
#define GSTR 104   // smem stride (halves) for G slice / hs rows: conflict-free

typedef unsigned long long ull;

// ---------------- scratch (__device__ globals; no allocation) ----------------
__device__ float g_X0[N_NODES * F0];
__device__ float g_bufA[N_NODES * HH];
__device__ float g_bufB[N_NODES * HH];
__device__ float g_msg[(size_t)N_EDGES * HH];                 // 23 MB
__device__ __half g_G[(size_t)N_NODES * NCP_MAX];             // 295 MB (fp16, o-major)
__device__ __half g_Ah[N_NODES * KP_MAX];                     // padded half A
__device__ __half g_BTh[NCP_MAX * KP_MAX];                    // padded half B^T
__device__ float g_agg[N_NODES * HH];                         // overflow-only accumulator
__device__ float g_pool[NGR * H2];
__device__ int   g_deg[N_NODES],  g_bucket[N_NODES * CAP];    // src buckets
__device__ int   g_deg2[N_NODES], g_bucket2[N_NODES * CAP];   // dst buckets
__device__ int   g_ovfS[N_EDGES], g_ovfD[N_EDGES];
__device__ int   g_ovfnS, g_ovfnD;

__device__ __forceinline__ uint32_t smem_u32(const void* p) {
    return (uint32_t)__cvta_generic_to_shared(p);
}
__device__ __forceinline__ void cp16(uint32_t dst, const void* src) {
    asm volatile("cp.async.cg.shared.global [%0], [%1], 16;" :: "r"(dst), "l"(src));
}

// ---------------- utility kernels ----------------
__global__ void zero_f(float* p, int n) {
    int i = blockIdx.x * blockDim.x + threadIdx.x;
    if (i < n) p[i] = 0.f;
}

__global__ void init_deg() {
    int i = blockIdx.x * blockDim.x + threadIdx.x;
    if (i < N_NODES) { g_deg[i] = 0; g_deg2[i] = 0; }
    if (i == 0) { g_ovfnS = 0; g_ovfnD = 0; }
}

__global__ void build_x0(const float* __restrict__ x, const float* __restrict__ pos) {
    int i = blockIdx.x * blockDim.x + threadIdx.x;
    if (i >= N_NODES * F0) return;
    int n = i / F0, c = i % F0;
    g_X0[i] = (c < 13) ? x[n * 13 + c] : pos[n * 3 + (c - 13)];
}

__global__ void bucket_build(const int* __restrict__ ei) {
    int e = blockIdx.x * blockDim.x + threadIdx.x;
    if (e >= N_EDGES) return;
    int s = ei[e];
    int slot = atomicAdd(&g_deg[s], 1);
    if (slot < CAP) g_bucket[s * CAP + slot] = e;
    else            g_ovfS[atomicAdd(&g_ovfnS, 1)] = e;
    int t = ei[N_EDGES + e];
    int slot2 = atomicAdd(&g_deg2[t], 1);
    if (slot2 < CAP) g_bucket2[t * CAP + slot2] = e;
    else             g_ovfD[atomicAdd(&g_ovfnD, 1)] = e;
}

// padded half A: Ah[n][k] = (k < in_c) ? Xin[n][k] : 0
__global__ void padX(const float* __restrict__ Xin, __half* __restrict__ Ah,
                     int in_c, int kp) {
    int idx = blockIdx.x * blockDim.x + threadIdx.x;
    if (idx >= N_NODES * kp) return;
    int n = idx / kp, k = idx - n * kp;
    Ah[idx] = __float2half((k < in_c) ? Xin[n * in_c + k] : 0.f);
}

// half BT, o-major G columns: col = o*96 + kh (kh<HH from w2); xb at out_c*96+o
__global__ void buildBT(const float* __restrict__ w2, const float* __restrict__ b2,
                        __half* __restrict__ BT, int in_c, int out_c, int ncp, int kp) {
    int idx = blockIdx.x * blockDim.x + threadIdx.x;
    if (idx >= ncp * kp) return;
    int col = idx / kp, k = idx - col * kp;
    float v = 0.f;
    if (k < in_c) {
        if (col < out_c * 96) {
            int o = col / 96, kh = col - o * 96;
            if (kh < HH)
                v = w2[((size_t)kh * in_c + k) * out_c + o];
        } else if (col < out_c * 96 + out_c) {
            v = b2[k * out_c + (col - out_c * 96)];
        }
    }
    BT[idx] = __float2half(v);
}

// ---------------- fp16 mma.sync GEMM, NCB column blocks, double-buffered B ----------------
__global__ __launch_bounds__(256)
void mma_gemm_h(const __half* __restrict__ A, const __half* __restrict__ BT,
                __half* __restrict__ C, int ncp, int kp, int lda) {
    extern __shared__ __half sm[];
    __half* As = sm;
    __half* BsBuf[2] = { sm + 128 * lda, sm + 2 * 128 * lda };

    const int tid = threadIdx.x;
    const int lane = tid & 31, wid = tid >> 5;
    const int rowBase = blockIdx.y * 128;
    const int colBase0 = blockIdx.x * (128 * NCB);
    const int warpRow = (wid & 3) * 32;
    const int warpCol = (wid >> 2) * 64;
    const int qr = lane >> 2, qk = lane & 3;
    const int nvec = kp >> 3;

    for (int t = tid; t < 128 * nvec; t += 256) {
        int row = t / nvec, j = (t - row * nvec) * 8;
        cp16(smem_u32(&As[row * lda + j]), &A[(size_t)(rowBase + row) * kp + j]);
    }
    for (int t = tid; t < 128 * nvec; t += 256) {
        int row = t / nvec, j = (t - row * nvec) * 8;
        cp16(smem_u32(&BsBuf[0][row * lda + j]), &BT[(size_t)(colBase0 + row) * kp + j]);
    }
    asm volatile("cp.async.commit_group;");

    for (int cb = 0; cb < NCB; cb++) {
        const __half* Bs = BsBuf[cb & 1];
        asm volatile("cp.async.wait_group 0;");
        __syncthreads();
        if (cb + 1 < NCB) {
            __half* Bn = BsBuf[(cb + 1) & 1];
            int colB = colBase0 + (cb + 1) * 128;
            for (int t = tid; t < 128 * nvec; t += 256) {
                int row = t / nvec, j = (t - row * nvec) * 8;
                cp16(smem_u32(&Bn[row * lda + j]), &BT[(size_t)(colB + row) * kp + j]);
            }
            asm volatile("cp.async.commit_group;");
        }

        float acc[2][8][4];
#pragma unroll
        for (int mt = 0; mt < 2; mt++)
#pragma unroll
            for (int nt = 0; nt < 8; nt++)
#pragma unroll
                for (int j = 0; j < 4; j++) acc[mt][nt][j] = 0.f;

        for (int ks = 0; ks < kp; ks += 16) {
            uint32_t a[2][4];
#pragma unroll
            for (int mt = 0; mt < 2; mt++) {
                int r = warpRow + mt * 16 + qr;
                a[mt][0] = *(const uint32_t*)&As[r * lda + ks + 2 * qk];
                a[mt][1] = *(const uint32_t*)&As[(r + 8) * lda + ks + 2 * qk];
                a[mt][2] = *(const uint32_t*)&As[r * lda + ks + 2 * qk + 8];
                a[mt][3] = *(const uint32_t*)&As[(r + 8) * lda + ks + 2 * qk + 8];
            }
#pragma unroll
            for (int nt = 0; nt < 8; nt++) {
                int c = warpCol + nt * 8 + qr;
                uint32_t b0 = *(const uint32_t*)&Bs[c * lda + ks + 2 * qk];
                uint32_t b1 = *(const uint32_t*)&Bs[c * lda + ks + 2 * qk + 8];
#pragma unroll
                for (int mt = 0; mt < 2; mt++) {
                    asm volatile(
                        "mma.sync.aligned.m16n8k16.row.col.f32.f16.f16.f32 "
                        "{%0,%1,%2,%3}, {%4,%5,%6,%7}, {%8,%9}, {%0,%1,%2,%3};"
                        : "+f"(acc[mt][nt][0]), "+f"(acc[mt][nt][1]),
                          "+f"(acc[mt][nt][2]), "+f"(acc[mt][nt][3])
                        : "r"(a[mt][0]), "r"(a[mt][1]), "r"(a[mt][2]), "r"(a[mt][3]),
                          "r"(b0), "r"(b1));
                }
            }
        }

        int colBase = colBase0 + cb * 128;
#pragma unroll
        for (int mt = 0; mt < 2; mt++) {
            int r = rowBase + warpRow + mt * 16 + qr;
#pragma unroll
            for (int nt = 0; nt < 8; nt++) {
                int c = colBase + warpCol + nt * 8 + qk * 2;
                __half2 v0 = __floats2half2_rn(acc[mt][nt][0], acc[mt][nt][1]);
                __half2 v1 = __floats2half2_rn(acc[mt][nt][2], acc[mt][nt][3]);
                *(__half2*)&C[(size_t)r * ncp + c] = v0;
                *(__half2*)&C[(size_t)(r + 8) * ncp + c] = v1;
            }
        }
        __syncthreads();
    }
}

// ---------------- per-src-node: edge MLP + tensor-core message ----------------
// G row layout: o-major, col = o*96 + k (k<90 valid, 90..95 zero); xb at out_c*96+o.
// Per batch of 16 edges: msg[16, out_c] = h[16, 96] @ Gslice[96, out_c] via m16n8k16.
__global__ void msg2(const int* __restrict__ ei, const float* __restrict__ ea,
                     const float* __restrict__ w1, const float* __restrict__ b1,
                     int out_c, int strideG,
                     const __half* __restrict__ G, float* __restrict__ msg) {
    int n = blockIdx.x;
    int d = g_deg[n];
    if (d == 0) return;
    if (d > CAP) d = CAP;

    const int OT = (out_c + 7) >> 3;      // 12 or 6 n-tiles
    const int NTW = OT / 3;               // 4 or 2 tiles per warp
    const int OR = OT * 8;                // staged o rows (96 or 48)

    __shared__ __align__(16) __half Gs[96 * GSTR];   // ≤ 20 KB
    __shared__ __align__(16) __half hs[16 * GSTR];   // 3.3 KB
    __shared__ float xbs[96];
    __shared__ float w1s[EF][HH];
    __shared__ float b1s[HH];
    __shared__ float eas[16][EF];
    __shared__ int eS[16];

    int tid = threadIdx.x;
    int lane = tid & 31, wid = tid >> 5;
    int qr = lane >> 2, qk = lane & 3;

    const __half* Grow = &G[(size_t)n * strideG];
    // stage G slice: row o -> Gs[o*GSTR + 0..95]; rows >= out_c zeroed
    for (int t = tid; t < OR * 12; t += 96) {
        int r = t / 12, j = (t - r * 12) * 8;
        uint4 v = make_uint4(0, 0, 0, 0);
        if (r < out_c) v = *(const uint4*)&Grow[r * 96 + j];
        *(uint4*)&Gs[r * GSTR + j] = v;
    }
    if (tid < 96) xbs[tid] = (tid < out_c) ? __half2float(Grow[out_c * 96 + tid]) : 0.f;
    for (int t = tid; t < EF * HH; t += 96) w1s[t / HH][t % HH] = w1[t];
    for (int t = tid; t < HH; t += 96) b1s[t] = b1[t];
    __syncthreads();

    for (int base = 0; base < d; base += 16) {
        int m = min(16, d - base);
        if (tid < m) eS[tid] = g_bucket[n * CAP + base + tid];
        __syncthreads();
        for (int t = tid; t < m * EF; t += 96)
            eas[t >> 3][t & 7] = ea[eS[t >> 3] * EF + (t & 7)];
        __syncthreads();
        // h: fp32 compute, fp16 store; rows >= m and k >= 90 zeroed
        int k = tid;
        if (k < 96) {
            for (int j = 0; j < 16; j++) {
                float s = 0.f;
                if (j < m && k < HH) {
                    s = b1s[k];
#pragma unroll
                    for (int q = 0; q < EF; q++) s = fmaf(eas[j][q], w1s[q][k], s);
                    s = fmaxf(s, 0.f);
                }
                hs[j * GSTR + k] = __float2half(s);
            }
        }
        __syncthreads();

        // tensor-core contraction: each warp handles NTW n-tiles
        float acc[4][4];
#pragma unroll
        for (int i = 0; i < 4; i++)
#pragma unroll
            for (int j = 0; j < 4; j++) acc[i][j] = 0.f;

        for (int ks = 0; ks < 96; ks += 16) {
            uint32_t a0 = *(const uint32_t*)&hs[qr * GSTR + ks + 2 * qk];
            uint32_t a1 = *(const uint32_t*)&hs[(qr + 8) * GSTR + ks + 2 * qk];
            uint32_t a2 = *(const uint32_t*)&hs[qr * GSTR + ks + 2 * qk + 8];
            uint32_t a3 = *(const uint32_t*)&hs[(qr + 8) * GSTR + ks + 2 * qk + 8];
#pragma unroll 4
            for (int i = 0; i < NTW; i++) {
                int orow = (wid * NTW + i) * 8 + qr;
                uint32_t b0 = *(const uint32_t*)&Gs[orow * GSTR + ks + 2 * qk];
                uint32_t b1v = *(const uint32_t*)&Gs[orow * GSTR + ks + 2 * qk + 8];
                asm volatile(
                    "mma.sync.aligned.m16n8k16.row.col.f32.f16.f16.f32 "
                    "{%0,%1,%2,%3}, {%4,%5,%6,%7}, {%8,%9}, {%0,%1,%2,%3};"
                    : "+f"(acc[i][0]), "+f"(acc[i][1]), "+f"(acc[i][2]), "+f"(acc[i][3])
                    : "r"(a0), "r"(a1), "r"(a2), "r"(a3), "r"(b0), "r"(b1v));
            }
        }

        // epilogue: c[row=edge][col=o] + xb
#pragma unroll 4
        for (int i = 0; i < NTW; i++) {
            int oA = (wid * NTW + i) * 8 + 2 * qk;
            float x0 = (oA < out_c) ? xbs[oA] : 0.f;
            float x1 = (oA + 1 < out_c) ? xbs[oA + 1] : 0.f;
            if (qr < m) {
                size_t rowb = (size_t)eS[qr] * out_c;
                if (oA < out_c)     msg[rowb + oA]     = acc[i][0] + x0;
                if (oA + 1 < out_c) msg[rowb + oA + 1] = acc[i][1] + x1;
            }
            if (qr + 8 < m) {
                size_t rowb = (size_t)eS[qr + 8] * out_c;
                if (oA < out_c)     msg[rowb + oA]     = acc[i][2] + x0;
                if (oA + 1 < out_c) msg[rowb + oA + 1] = acc[i][3] + x1;
            }
        }
        __syncthreads();
    }
}

// src-overflow fallback (o-major G layout; normally zero iterations)
__global__ void msg_ovfS(const int* __restrict__ ei, const float* __restrict__ ea,
                         const float* __restrict__ w1, const float* __restrict__ b1,
                         int out_c, int strideG,
                         const __half* __restrict__ G, float* __restrict__ msg) {
    __shared__ float hs[HH];
    for (int idx = blockIdx.x; idx < g_ovfnS; idx += gridDim.x) {
        int e = g_ovfS[idx];
        int n = ei[e];
        int k = threadIdx.x;
        if (k < HH) {
            float s = b1[k];
#pragma unroll
            for (int q = 0; q < EF; q++) s = fmaf(ea[e * EF + q], w1[q * HH + k], s);
            hs[k] = fmaxf(s, 0.f);
        }
        __syncthreads();
        const __half* Grow = &G[(size_t)n * strideG];
        int o = threadIdx.x;
        if (o < out_c) {
            float acc = __half2float(Grow[out_c * 96 + o]);
            for (int kk = 0; kk < HH; kk++)
                acc = fmaf(hs[kk], __half2float(Grow[o * 96 + kk]), acc);
            msg[(size_t)e * out_c + o] = acc;
        }
        __syncthreads();
    }
}

// dst-overflow fallback (normally zero iterations)
__global__ void agg_ovfD(const int* __restrict__ ei, int out_c,
                         const float* __restrict__ msg, float* __restrict__ agg) {
    for (int idx = blockIdx.x; idx < g_ovfnD; idx += gridDim.x) {
        int e = g_ovfD[idx];
        int t = ei[N_EDGES + e];
        int o = threadIdx.x;
        if (o < out_c) atomicAdd(&agg[t * out_c + o], msg[(size_t)e * out_c + o]);
    }
}

// per-dst-node: gather msgs + root + bias + relu (fused finalize; optional pool)
__global__ void aggfin(const float* __restrict__ Xin, float* __restrict__ Xout,
                       const float* __restrict__ root, const float* __restrict__ bias,
                       const float* __restrict__ agg, const float* __restrict__ msg,
                       int in_c, int out_c,
                       const int* __restrict__ batch, float* __restrict__ pool) {
    int n = blockIdx.x;
    __shared__ float xs[HH];
    __shared__ int eS[CAP];
    int tid = threadIdx.x;
    for (int t = tid; t < in_c; t += blockDim.x) xs[t] = Xin[n * in_c + t];
    int d = g_deg2[n];
    if (d > CAP) d = CAP;
    for (int t = tid; t < d; t += blockDim.x) eS[t] = g_bucket2[n * CAP + t];
    __syncthreads();
    int o = tid;
    if (o < out_c) {
        float acc = agg[n * out_c + o] + bias[o];
        for (int j = 0; j < d; j++)
            acc += msg[(size_t)eS[j] * out_c + o];
        for (int i = 0; i < in_c; i++)
            acc = fmaf(xs[i], __ldg(&root[i * out_c + o]), acc);
        acc = fmaxf(acc, 0.f);
        if (pool) atomicAdd(&pool[batch[n] * out_c + o], acc);
        else      Xout[n * out_c + o] = acc;
    }
}

__global__ void head_k(const float* __restrict__ fc1w, const float* __restrict__ fc1b,
                       const float* __restrict__ outw, const float* __restrict__ outb,
                       float* __restrict__ out) {
    int g = blockIdx.x;
    __shared__ float ps[H2];
    __shared__ float fs[HH];
    for (int t = threadIdx.x; t < H2; t += blockDim.x) ps[t] = g_pool[g * H2 + t];
    __syncthreads();
    int o = threadIdx.x;
    if (o < HH) {
        float a = fc1b[o];
        for (int i = 0; i < H2; i++) a = fmaf(ps[i], fc1w[i * HH + o], a);
        fs[o] = fmaxf(a, 0.f);
    }
    __syncthreads();
    if (threadIdx.x == 0) {
        float s = outb[0];
        for (int q = 0; q < HH; q++) s = fmaf(fs[q], outw[q], s);
        out[g] = s;
    }
}

// ---------------- host orchestration ----------------
static void run_layer(const float* Xin, float* Xout, int in_c, int out_c,
                      const float* w1, const float* b1, const float* w2, const float* b2,
                      const float* root, const float* bias,
                      const float* ea, const int* ei,
                      __half* G, __half* Ah, __half* BTh, float* agg, float* msg,
                      const int* batch, float* pool) {
    int ncp = ((out_c * 96 + out_c) + 511) & ~511;  // 9216 / 9216 / 4608
    int kp = ((in_c + 31) & ~31);                   // 32 / 96 / 96
    int lda = kp + 8;

    padX<<<(N_NODES * kp + 255) / 256, 256>>>(Xin, Ah, in_c, kp);
    buildBT<<<(ncp * kp + 255) / 256, 256>>>(w2, b2, BTh, in_c, out_c, ncp, kp);
    {
        dim3 gr(ncp / (128 * NCB), N_NODES / 128);
        size_t smem = (size_t)3 * 128 * lda * sizeof(__half);
        mma_gemm_h<<<gr, 256, smem>>>(Ah, BTh, G, ncp, kp, lda);
    }
    msg2<<<N_NODES, 96>>>(ei, ea, w1, b1, out_c, ncp, G, msg);
    msg_ovfS<<<64, 96>>>(ei, ea, w1, b1, out_c, ncp, G, msg);
    zero_f<<<(N_NODES * out_c + 255) / 256, 256>>>(agg, N_NODES * out_c);
    agg_ovfD<<<64, 96>>>(ei, out_c, msg, agg);
    aggfin<<<N_NODES, 96>>>(Xin, Xout, root, bias, agg, msg, in_c, out_c, batch, pool);
}

extern "C" void kernel_launch(void* const* d_in, const int* in_sizes, int n_in,
                              void* d_out, int out_size) {
    const float* x    = (const float*)d_in[0];
    const float* pos  = (const float*)d_in[1];
    const float* ea   = (const float*)d_in[2];
    const int*   ei   = (const int*)  d_in[3];
    const int*   bat  = (const int*)  d_in[4];
    const float* c1w1 = (const float*)d_in[5];
    const float* c1b1 = (const float*)d_in[6];
    const float* c1w2 = (const float*)d_in[7];
    const float* c1b2 = (const float*)d_in[8];
    const float* c1r  = (const float*)d_in[9];
    const float* c1b  = (const float*)d_in[10];
    const float* c2w1 = (const float*)d_in[11];
    const float* c2b1 = (const float*)d_in[12];
    const float* c2w2 = (const float*)d_in[13];
    const float* c2b2 = (const float*)d_in[14];
    const float* c2r  = (const float*)d_in[15];
    const float* c2b  = (const float*)d_in[16];
    const float* c3w1 = (const float*)d_in[17];
    const float* c3b1 = (const float*)d_in[18];
    const float* c3w2 = (const float*)d_in[19];
    const float* c3b2 = (const float*)d_in[20];
    const float* c3r  = (const float*)d_in[21];
    const float* c3b  = (const float*)d_in[22];
    const float* f1w  = (const float*)d_in[23];
    const float* f1b  = (const float*)d_in[24];
    const float* ow   = (const float*)d_in[25];
    const float* ob   = (const float*)d_in[26];
    float* out = (float*)d_out;

    cudaFuncSetAttribute(mma_gemm_h, cudaFuncAttributeMaxDynamicSharedMemorySize,
                         3 * 128 * (KP_MAX + 8) * (int)sizeof(__half));

    void *pX0, *pA, *pB, *pG, *pAh, *pBTh, *pagg, *pmsg, *ppool;
    cudaGetSymbolAddress(&pX0, g_X0);
    cudaGetSymbolAddress(&pA, g_bufA);
    cudaGetSymbolAddress(&pB, g_bufB);
    cudaGetSymbolAddress(&pG, g_G);
    cudaGetSymbolAddress(&pAh, g_Ah);
    cudaGetSymbolAddress(&pBTh, g_BTh);
    cudaGetSymbolAddress(&pagg, g_agg);
    cudaGetSymbolAddress(&pmsg, g_msg);
    cudaGetSymbolAddress(&ppool, g_pool);
    float* X0  = (float*)pX0;
    float* bufA= (float*)pA;
    float* bufB= (float*)pB;
    __half* G  = (__half*)pG;
    __half* Ah = (__half*)pAh;
    __half* BTh= (__half*)pBTh;
    float* agg = (float*)pagg;
    float* msg = (float*)pmsg;
    float* pool= (float*)ppool;

    build_x0<<<(N_NODES * F0 + 255) / 256, 256>>>(x, pos);
    init_deg<<<(N_NODES + 255) / 256, 256>>>();
    bucket_build<<<(N_EDGES + 255) / 256, 256>>>(ei);
    zero_f<<<(NGR * H2 + 255) / 256, 256>>>(pool, NGR * H2);

    // layer 1: 16 -> 90
    run_layer(X0, bufA, F0, HH, c1w1, c1b1, c1w2, c1b2, c1r, c1b, ea, ei,
              G, Ah, BTh, agg, msg, nullptr, nullptr);
    // layer 2: 90 -> 90
    run_layer(bufA, bufB, HH, HH, c2w1, c2b1, c2w2, c2b2, c2r, c2b, ea, ei,
              G, Ah, BTh, agg, msg, nullptr, nullptr);
    // layer 3: 90 -> 45, fused global_add_pool
    run_layer(bufB, bufA, HH, H2, c3w1, c3b1, c3w2, c3b2, c3r, c3b, ea, ei,
              G, Ah, BTh, agg, msg, bat, pool);

    head_k<<<NGR, 96>>>(f1w, f1b, ow, ob, out);
}

// round 17
// speedup vs baseline: 1.1976x; 1.1976x over previous
#include <cuda_runtime.h>
#include <cuda_fp16.h>
#include <math.h>
#include <stdint.h>

#define N_NODES 16000
#define N_EDGES 64000
#define HH 90
#define F0 16
#define EF 8
#define NGR 512
#define H2 45
#define CAP 64
#define NCP_MAX 8192
#define KP_MAX 96
#define NCB 4
#define EB 4   // edge batch (matched to E[deg]≈4)

typedef unsigned long long ull;

// ---------------- scratch (__device__ globals; no allocation) ----------------
__device__ float g_X0[N_NODES * F0];
__device__ float g_bufA[N_NODES * HH];
__device__ float g_bufB[N_NODES * HH];
__device__ float g_msg[(size_t)N_EDGES * HH];                 // 23 MB
__device__ __half g_G[(size_t)N_NODES * NCP_MAX];             // 262 MB (fp16)
__device__ __half g_Ah[N_NODES * KP_MAX];                     // padded half A
__device__ __half g_BTh[NCP_MAX * KP_MAX];                    // padded half B^T
__device__ float g_agg[N_NODES * HH];                         // overflow-only accumulator
__device__ float g_pool[NGR * H2];
__device__ int   g_deg[N_NODES],  g_bucket[N_NODES * CAP];    // src buckets
__device__ int   g_deg2[N_NODES], g_bucket2[N_NODES * CAP];   // dst buckets
__device__ int   g_ovfS[N_EDGES], g_ovfD[N_EDGES];
__device__ int   g_ovfnS, g_ovfnD;

__device__ __forceinline__ uint32_t smem_u32(const void* p) {
    return (uint32_t)__cvta_generic_to_shared(p);
}
__device__ __forceinline__ void cp16(uint32_t dst, const void* src) {
    asm volatile("cp.async.cg.shared.global [%0], [%1], 16;" :: "r"(dst), "l"(src));
}
__device__ __forceinline__ ull packf2(float lo, float hi) {
    ull r; asm("mov.b64 %0, {%1, %2};" : "=l"(r) : "f"(lo), "f"(hi)); return r;
}
__device__ __forceinline__ void fma2(ull& d, ull a, ull b) {
    asm("fma.rn.f32x2 %0, %1, %2, %0;" : "+l"(d) : "l"(a), "l"(b));
}

// ---------------- utility kernels (round-15 proven orchestration) ----------------
__global__ void zero_f(float* p, int n) {
    int i = blockIdx.x * blockDim.x + threadIdx.x;
    if (i < n) p[i] = 0.f;
}

__global__ void init_deg() {
    int i = blockIdx.x * blockDim.x + threadIdx.x;
    if (i < N_NODES) { g_deg[i] = 0; g_deg2[i] = 0; }
    if (i == 0) { g_ovfnS = 0; g_ovfnD = 0; }
}

__global__ void build_x0(const float* __restrict__ x, const float* __restrict__ pos) {
    int i = blockIdx.x * blockDim.x + threadIdx.x;
    if (i >= N_NODES * F0) return;
    int n = i / F0, c = i % F0;
    g_X0[i] = (c < 13) ? x[n * 13 + c] : pos[n * 3 + (c - 13)];
}

__global__ void bucket_build(const int* __restrict__ ei) {
    int e = blockIdx.x * blockDim.x + threadIdx.x;
    if (e >= N_EDGES) return;
    int s = ei[e];
    int slot = atomicAdd(&g_deg[s], 1);
    if (slot < CAP) g_bucket[s * CAP + slot] = e;
    else            g_ovfS[atomicAdd(&g_ovfnS, 1)] = e;
    int t = ei[N_EDGES + e];
    int slot2 = atomicAdd(&g_deg2[t], 1);
    if (slot2 < CAP) g_bucket2[t * CAP + slot2] = e;
    else             g_ovfD[atomicAdd(&g_ovfnD, 1)] = e;
}

// padded half A: Ah[n][k] = (k < in_c) ? Xin[n][k] : 0
__global__ void padX(const float* __restrict__ Xin, __half* __restrict__ Ah,
                     int in_c, int kp) {
    int idx = blockIdx.x * blockDim.x + threadIdx.x;
    if (idx >= N_NODES * kp) return;
    int n = idx / kp, k = idx - n * kp;
    Ah[idx] = __float2half((k < in_c) ? Xin[n * in_c + k] : 0.f);
}

// half BT: cols [0, HH*out) from w2; cols [HH*out, HH*out+out) from b2; else 0
__global__ void buildBT(const float* __restrict__ w2, const float* __restrict__ b2,
                        __half* __restrict__ BT, int in_c, int out_c, int ncp, int kp) {
    int idx = blockIdx.x * blockDim.x + threadIdx.x;
    if (idx >= ncp * kp) return;
    int col = idx / kp, k = idx - col * kp;
    float v = 0.f;
    if (k < in_c) {
        if (col < HH * out_c) {
            int kk = col / out_c, o = col - kk * out_c;
            v = w2[((size_t)kk * in_c + k) * out_c + o];
        } else if (col < HH * out_c + out_c) {
            v = b2[k * out_c + (col - HH * out_c)];
        }
    }
    BT[idx] = __float2half(v);
}

// ---------------- fp16 mma.sync GEMM, NCB column blocks per CTA, double-buffered B ----------------
__global__ __launch_bounds__(256)
void mma_gemm_h(const __half* __restrict__ A, const __half* __restrict__ BT,
                __half* __restrict__ C, int ncp, int kp, int lda) {
    extern __shared__ __half sm[];
    __half* As = sm;
    __half* BsBuf[2] = { sm + 128 * lda, sm + 2 * 128 * lda };

    const int tid = threadIdx.x;
    const int lane = tid & 31, wid = tid >> 5;
    const int rowBase = blockIdx.y * 128;
    const int colBase0 = blockIdx.x * (128 * NCB);
    const int warpRow = (wid & 3) * 32;
    const int warpCol = (wid >> 2) * 64;
    const int qr = lane >> 2, qk = lane & 3;
    const int nvec = kp >> 3;

    for (int t = tid; t < 128 * nvec; t += 256) {
        int row = t / nvec, j = (t - row * nvec) * 8;
        cp16(smem_u32(&As[row * lda + j]), &A[(size_t)(rowBase + row) * kp + j]);
    }
    for (int t = tid; t < 128 * nvec; t += 256) {
        int row = t / nvec, j = (t - row * nvec) * 8;
        cp16(smem_u32(&BsBuf[0][row * lda + j]), &BT[(size_t)(colBase0 + row) * kp + j]);
    }
    asm volatile("cp.async.commit_group;");

    for (int cb = 0; cb < NCB; cb++) {
        const __half* Bs = BsBuf[cb & 1];
        asm volatile("cp.async.wait_group 0;");
        __syncthreads();
        if (cb + 1 < NCB) {
            __half* Bn = BsBuf[(cb + 1) & 1];
            int colB = colBase0 + (cb + 1) * 128;
            for (int t = tid; t < 128 * nvec; t += 256) {
                int row = t / nvec, j = (t - row * nvec) * 8;
                cp16(smem_u32(&Bn[row * lda + j]), &BT[(size_t)(colB + row) * kp + j]);
            }
            asm volatile("cp.async.commit_group;");
        }

        float acc[2][8][4];
#pragma unroll
        for (int mt = 0; mt < 2; mt++)
#pragma unroll
            for (int nt = 0; nt < 8; nt++)
#pragma unroll
                for (int j = 0; j < 4; j++) acc[mt][nt][j] = 0.f;

        for (int ks = 0; ks < kp; ks += 16) {
            uint32_t a[2][4];
#pragma unroll
            for (int mt = 0; mt < 2; mt++) {
                int r = warpRow + mt * 16 + qr;
                a[mt][0] = *(const uint32_t*)&As[r * lda + ks + 2 * qk];
                a[mt][1] = *(const uint32_t*)&As[(r + 8) * lda + ks + 2 * qk];
                a[mt][2] = *(const uint32_t*)&As[r * lda + ks + 2 * qk + 8];
                a[mt][3] = *(const uint32_t*)&As[(r + 8) * lda + ks + 2 * qk + 8];
            }
#pragma unroll
            for (int nt = 0; nt < 8; nt++) {
                int c = warpCol + nt * 8 + qr;
                uint32_t b0 = *(const uint32_t*)&Bs[c * lda + ks + 2 * qk];
                uint32_t b1 = *(const uint32_t*)&Bs[c * lda + ks + 2 * qk + 8];
#pragma unroll
                for (int mt = 0; mt < 2; mt++) {
                    asm volatile(
                        "mma.sync.aligned.m16n8k16.row.col.f32.f16.f16.f32 "
                        "{%0,%1,%2,%3}, {%4,%5,%6,%7}, {%8,%9}, {%0,%1,%2,%3};"
                        : "+f"(acc[mt][nt][0]), "+f"(acc[mt][nt][1]),
                          "+f"(acc[mt][nt][2]), "+f"(acc[mt][nt][3])
                        : "r"(a[mt][0]), "r"(a[mt][1]), "r"(a[mt][2]), "r"(a[mt][3]),
                          "r"(b0), "r"(b1));
                }
            }
        }

        int colBase = colBase0 + cb * 128;
#pragma unroll
        for (int mt = 0; mt < 2; mt++) {
            int r = rowBase + warpRow + mt * 16 + qr;
#pragma unroll
            for (int nt = 0; nt < 8; nt++) {
                int c = colBase + warpCol + nt * 8 + qk * 2;
                __half2 v0 = __floats2half2_rn(acc[mt][nt][0], acc[mt][nt][1]);
                __half2 v1 = __floats2half2_rn(acc[mt][nt][2], acc[mt][nt][3]);
                *(__half2*)&C[(size_t)r * ncp + c] = v0;
                *(__half2*)&C[(size_t)(r + 8) * ncp + c] = v1;
            }
        }
        __syncthreads();
    }
}

// ---------------- per-src-node: edge MLP + message (FFMA2, batch=4) ----------------
__global__ void msg2(const int* __restrict__ ei, const float* __restrict__ ea,
                     const float* __restrict__ w1, const float* __restrict__ b1,
                     int out_c, int strideG,
                     const __half* __restrict__ G, float* __restrict__ msg) {
    int n = blockIdx.x;
    int d = g_deg[n];
    if (d == 0) return;
    if (d > CAP) d = CAP;
    __shared__ __align__(16) __half Gs[NCP_MAX];     // 16 KB
    __shared__ __align__(16) float hs[EB][HH];       // stride 360 B: 8B-safe at even kk
    __shared__ float w1s[EF][HH];
    __shared__ float b1s[HH];
    __shared__ float eas[EB][EF];
    __shared__ int eS[EB];
    int tid = threadIdx.x;

    const __half* Grow = &G[(size_t)n * strideG];
    int nvec = (HH * out_c + out_c + 7) >> 3;
    for (int t = tid; t < nvec; t += blockDim.x)
        *(uint4*)&Gs[t * 8] = *(const uint4*)&Grow[t * 8];
    for (int t = tid; t < EF * HH; t += blockDim.x) w1s[t / HH][t % HH] = w1[t];
    for (int t = tid; t < HH; t += blockDim.x) b1s[t] = b1[t];
    __syncthreads();
    float xbv = (tid < out_c) ? __half2float(Gs[HH * out_c + tid]) : 0.f;

    for (int base = 0; base < d; base += EB) {
        int m = min(EB, d - base);
        __syncthreads();
        if (tid < m) eS[tid] = g_bucket[n * CAP + base + tid];
        __syncthreads();
        for (int t = tid; t < m * EF; t += blockDim.x)
            eas[t >> 3][t & 7] = ea[eS[t >> 3] * EF + (t & 7)];
        __syncthreads();
        int k = tid;
        if (k < HH) {
            for (int j = 0; j < m; j++) {
                float s = b1s[k];
#pragma unroll
                for (int q = 0; q < EF; q++) s = fmaf(eas[j][q], w1s[q][k], s);
                hs[j][k] = fmaxf(s, 0.f);
            }
        }
        __syncthreads();
        int o = tid;
        if (o < out_c) {
            ull acc2[EB];
#pragma unroll
            for (int j = 0; j < EB; j++) acc2[j] = 0ULL;
            for (int kk = 0; kk < HH; kk += 2) {       // HH=90 even
                float g0 = __half2float(Gs[kk * out_c + o]);
                float g1 = __half2float(Gs[(kk + 1) * out_c + o]);
                ull gp = packf2(g0, g1);
#pragma unroll
                for (int j = 0; j < EB; j++) {
                    ull h2 = *(const ull*)&hs[j][kk];
                    fma2(acc2[j], h2, gp);
                }
            }
            for (int j = 0; j < m; j++) {
                float lo, hi;
                asm("mov.b64 {%0, %1}, %2;" : "=f"(lo), "=f"(hi) : "l"(acc2[j]));
                msg[(size_t)eS[j] * out_c + o] = lo + hi + xbv;
            }
        }
    }
}

// src-overflow fallback (normally zero iterations)
__global__ void msg_ovfS(const int* __restrict__ ei, const float* __restrict__ ea,
                         const float* __restrict__ w1, const float* __restrict__ b1,
                         int out_c, int strideG,
                         const __half* __restrict__ G, float* __restrict__ msg) {
    __shared__ float hs[HH];
    for (int idx = blockIdx.x; idx < g_ovfnS; idx += gridDim.x) {
        int e = g_ovfS[idx];
        int n = ei[e];
        int k = threadIdx.x;
        if (k < HH) {
            float s = b1[k];
#pragma unroll
            for (int q = 0; q < EF; q++) s = fmaf(ea[e * EF + q], w1[q * HH + k], s);
            hs[k] = fmaxf(s, 0.f);
        }
        __syncthreads();
        const __half* Grow = &G[(size_t)n * strideG];
        int o = threadIdx.x;
        if (o < out_c) {
            float acc = __half2float(Grow[HH * out_c + o]);
            for (int kk = 0; kk < HH; kk++)
                acc = fmaf(hs[kk], __half2float(Grow[kk * out_c + o]), acc);
            msg[(size_t)e * out_c + o] = acc;
        }
        __syncthreads();
    }
}

// dst-overflow fallback (normally zero iterations)
__global__ void agg_ovfD(const int* __restrict__ ei, int out_c,
                         const float* __restrict__ msg, float* __restrict__ agg) {
    for (int idx = blockIdx.x; idx < g_ovfnD; idx += gridDim.x) {
        int e = g_ovfD[idx];
        int t = ei[N_EDGES + e];
        int o = threadIdx.x;
        if (o < out_c) atomicAdd(&agg[t * out_c + o], msg[(size_t)e * out_c + o]);
    }
}

// per-dst-node: gather msgs + root + bias + relu (fused finalize; optional pool)
__global__ void aggfin(const float* __restrict__ Xin, float* __restrict__ Xout,
                       const float* __restrict__ root, const float* __restrict__ bias,
                       const float* __restrict__ agg, const float* __restrict__ msg,
                       int in_c, int out_c,
                       const int* __restrict__ batch, float* __restrict__ pool) {
    int n = blockIdx.x;
    __shared__ float xs[HH];
    __shared__ int eS[CAP];
    int tid = threadIdx.x;
    for (int t = tid; t < in_c; t += blockDim.x) xs[t] = Xin[n * in_c + t];
    int d = g_deg2[n];
    if (d > CAP) d = CAP;
    for (int t = tid; t < d; t += blockDim.x) eS[t] = g_bucket2[n * CAP + t];
    __syncthreads();
    int o = tid;
    if (o < out_c) {
        float acc = agg[n * out_c + o] + bias[o];
        for (int j = 0; j < d; j++)
            acc += msg[(size_t)eS[j] * out_c + o];
        for (int i = 0; i < in_c; i++)
            acc = fmaf(xs[i], __ldg(&root[i * out_c + o]), acc);
        acc = fmaxf(acc, 0.f);
        if (pool) atomicAdd(&pool[batch[n] * out_c + o], acc);
        else      Xout[n * out_c + o] = acc;
    }
}

__global__ void head_k(const float* __restrict__ fc1w, const float* __restrict__ fc1b,
                       const float* __restrict__ outw, const float* __restrict__ outb,
                       float* __restrict__ out) {
    int g = blockIdx.x;
    __shared__ float ps[H2];
    __shared__ float fs[HH];
    for (int t = threadIdx.x; t < H2; t += blockDim.x) ps[t] = g_pool[g * H2 + t];
    __syncthreads();
    int o = threadIdx.x;
    if (o < HH) {
        float a = fc1b[o];
        for (int i = 0; i < H2; i++) a = fmaf(ps[i], fc1w[i * HH + o], a);
        fs[o] = fmaxf(a, 0.f);
    }
    __syncthreads();
    if (threadIdx.x == 0) {
        float s = outb[0];
        for (int q = 0; q < HH; q++) s = fmaf(fs[q], outw[q], s);
        out[g] = s;
    }
}

// ---------------- host orchestration (round-15 proven) ----------------
static void run_layer(const float* Xin, float* Xout, int in_c, int out_c,
                      const float* w1, const float* b1, const float* w2, const float* b2,
                      const float* root, const float* bias,
                      const float* ea, const int* ei,
                      __half* G, __half* Ah, __half* BTh, float* agg, float* msg,
                      const int* batch, float* pool) {
    int ncp = (HH * out_c + out_c + 127) & ~127;   // 8192 / 8192 / 4096
    int kp = ((in_c + 31) & ~31);                  // 32 / 96 / 96
    int lda = kp + 8;

    padX<<<(N_NODES * kp + 255) / 256, 256>>>(Xin, Ah, in_c, kp);
    buildBT<<<(ncp * kp + 255) / 256, 256>>>(w2, b2, BTh, in_c, out_c, ncp, kp);
    {
        dim3 gr(ncp / (128 * NCB), N_NODES / 128);
        size_t smem = (size_t)3 * 128 * lda * sizeof(__half);
        mma_gemm_h<<<gr, 256, smem>>>(Ah, BTh, G, ncp, kp, lda);
    }
    msg2<<<N_NODES, 96>>>(ei, ea, w1, b1, out_c, ncp, G, msg);
    msg_ovfS<<<64, 96>>>(ei, ea, w1, b1, out_c, ncp, G, msg);
    zero_f<<<(N_NODES * out_c + 255) / 256, 256>>>(agg, N_NODES * out_c);
    agg_ovfD<<<64, 96>>>(ei, out_c, msg, agg);
    aggfin<<<N_NODES, 96>>>(Xin, Xout, root, bias, agg, msg, in_c, out_c, batch, pool);
}

extern "C" void kernel_launch(void* const* d_in, const int* in_sizes, int n_in,
                              void* d_out, int out_size) {
    const float* x    = (const float*)d_in[0];
    const float* pos  = (const float*)d_in[1];
    const float* ea   = (const float*)d_in[2];
    const int*   ei   = (const int*)  d_in[3];
    const int*   bat  = (const int*)  d_in[4];
    const float* c1w1 = (const float*)d_in[5];
    const float* c1b1 = (const float*)d_in[6];
    const float* c1w2 = (const float*)d_in[7];
    const float* c1b2 = (const float*)d_in[8];
    const float* c1r  = (const float*)d_in[9];
    const float* c1b  = (const float*)d_in[10];
    const float* c2w1 = (const float*)d_in[11];
    const float* c2b1 = (const float*)d_in[12];
    const float* c2w2 = (const float*)d_in[13];
    const float* c2b2 = (const float*)d_in[14];
    const float* c2r  = (const float*)d_in[15];
    const float* c2b  = (const float*)d_in[16];
    const float* c3w1 = (const float*)d_in[17];
    const float* c3b1 = (const float*)d_in[18];
    const float* c3w2 = (const float*)d_in[19];
    const float* c3b2 = (const float*)d_in[20];
    const float* c3r  = (const float*)d_in[21];
    const float* c3b  = (const float*)d_in[22];
    const float* f1w  = (const float*)d_in[23];
    const float* f1b  = (const float*)d_in[24];
    const float* ow   = (const float*)d_in[25];
    const float* ob   = (const float*)d_in[26];
    float* out = (float*)d_out;

    cudaFuncSetAttribute(mma_gemm_h, cudaFuncAttributeMaxDynamicSharedMemorySize,
                         3 * 128 * (KP_MAX + 8) * (int)sizeof(__half));

    void *pX0, *pA, *pB, *pG, *pAh, *pBTh, *pagg, *pmsg, *ppool;
    cudaGetSymbolAddress(&pX0, g_X0);
    cudaGetSymbolAddress(&pA, g_bufA);
    cudaGetSymbolAddress(&pB, g_bufB);
    cudaGetSymbolAddress(&pG, g_G);
    cudaGetSymbolAddress(&pAh, g_Ah);
    cudaGetSymbolAddress(&pBTh, g_BTh);
    cudaGetSymbolAddress(&pagg, g_agg);
    cudaGetSymbolAddress(&pmsg, g_msg);
    cudaGetSymbolAddress(&ppool, g_pool);
    float* X0  = (float*)pX0;
    float* bufA= (float*)pA;
    float* bufB= (float*)pB;
    __half* G  = (__half*)pG;
    __half* Ah = (__half*)pAh;
    __half* BTh= (__half*)pBTh;
    float* agg = (float*)pagg;
    float* msg = (float*)pmsg;
    float* pool= (float*)ppool;

    build_x0<<<(N_NODES * F0 + 255) / 256, 256>>>(x, pos);
    init_deg<<<(N_NODES + 255) / 256, 256>>>();
    bucket_build<<<(N_EDGES + 255) / 256, 256>>>(ei);
    zero_f<<<(NGR * H2 + 255) / 256, 256>>>(pool, NGR * H2);

    // layer 1: 16 -> 90
    run_layer(X0, bufA, F0, HH, c1w1, c1b1, c1w2, c1b2, c1r, c1b, ea, ei,
              G, Ah, BTh, agg, msg, nullptr, nullptr);
    // layer 2: 90 -> 90
    run_layer(bufA, bufB, HH, HH, c2w1, c2b1, c2w2, c2b2, c2r, c2b, ea, ei,
              G, Ah, BTh, agg, msg, nullptr, nullptr);
    // layer 3: 90 -> 45, fused global_add_pool
    run_layer(bufB, bufA, HH, H2, c3w1, c3b1, c3w2, c3b2, c3r, c3b, ea, ei,
              G, Ah, BTh, agg, msg, bat, pool);

    head_k<<<NGR, 96>>>(f1w, f1b, ow, ob, out);
}